// round 1
// baseline (speedup 1.0000x reference)
#include <cuda_runtime.h>
#include <cuda_bf16.h>
#include <math.h>

// ---------------- static problem config ----------------
#define NB    2          // batch
#define CIN   64
#define COUT  128
#define KK    3
#define TAPS  27
#define DD    16
#define HH    28
#define WW    28
#define DP    18         // padded
#define HP    30
#define WP    30
#define VOX   (DD*HH*WW)         // 12544
#define PTOT  (NB*VOX)           // 25088
#define OC1   81                 // offset conv out channels (3*27)
#define OC1P  96                 // padded to 96
#define BN_EPS 1e-5f

#define BNPOS 64                 // position tile
#define NBLK  (PTOT/BNPOS)       // 392 (exact)

// ---------------- scratch (device globals; no allocation allowed) ----------------
__device__ float g_xpt[NB*DP*HP*WP*CIN];       // padded channels-last x   (~8.3MB)
__device__ float g_wofft[TAPS*CIN*OC1P];       // offset conv weights [tap][c][oc]
__device__ float g_wt[TAPS*CIN*COUT];          // deform conv weights [tap][c][oc]
__device__ float g_off[OC1*PTOT];              // offsets [ch][pos]
__device__ float g_y[COUT*PTOT];               // pre-BN output [co][pos]
__device__ float g_stats[2*COUT];              // mean, inv-std

// ---------------- K0: pad + transpose to channels-last ----------------
__global__ void k_pad(const float* __restrict__ x) {
    int idx = blockIdx.x * blockDim.x + threadIdx.x;
    const int total = NB*DP*HP*WP*CIN;
    if (idx >= total) return;
    int c = idx % CIN;
    int t = idx / CIN;
    int wx = t % WP; t /= WP;
    int hy = t % HP; t /= HP;
    int dz = t % DP; int n = t / DP;
    float v = 0.f;
    if (dz >= 1 && dz <= DD && hy >= 1 && hy <= HH && wx >= 1 && wx <= WW) {
        v = x[(((n*CIN + c)*DD + (dz-1))*HH + (hy-1))*WW + (wx-1)];
    }
    g_xpt[idx] = v;
}

// ---------------- K0b/K0c: weight transposes ----------------
__global__ void k_wofft(const float* __restrict__ w_off) {
    int idx = blockIdx.x * blockDim.x + threadIdx.x;
    const int total = TAPS*CIN*OC1P;
    if (idx >= total) return;
    int oc = idx % OC1P;
    int t = idx / OC1P;
    int c = t % CIN;
    int tap = t / CIN;
    float v = 0.f;
    if (oc < OC1) v = w_off[(oc*CIN + c)*TAPS + tap];
    g_wofft[idx] = v;
}

__global__ void k_wtrans(const float* __restrict__ w_conv) {
    int idx = blockIdx.x * blockDim.x + threadIdx.x;
    const int total = TAPS*CIN*COUT;
    if (idx >= total) return;
    int oc = idx % COUT;
    int t = idx / COUT;
    int c = t % CIN;
    int tap = t / CIN;
    g_wt[idx] = w_conv[(oc*CIN + c)*TAPS + tap];
}

// ---------------- K1: offset conv (GEMM 96 x 64pos, K=1728, im2col gather) --------
__global__ __launch_bounds__(256) void k_offconv(const float* __restrict__ b_off) {
    __shared__ float As[CIN*OC1P];   // 24KB  [c][oc]
    __shared__ float Bs[CIN*BNPOS];  // 16KB  [c][pos]

    const int tid = threadIdx.x;
    const int pos0 = blockIdx.x * BNPOS;
    const int tn = tid & 15;          // 16 col groups * 4 pos
    const int tm = tid >> 4;          // 16 row groups * 6 oc

    // gather role
    const int posl = tid & 63;
    const int c0 = (tid >> 6) * 16;   // 4 groups of 16 channels
    const int pos = pos0 + posl;
    const int n = pos / VOX;
    const int vox = pos % VOX;
    const int dz = vox / (HH*WW);
    const int r  = vox % (HH*WW);
    const int hy = r / WW;
    const int wx = r % WW;

    float acc[6][4];
    #pragma unroll
    for (int i = 0; i < 6; ++i)
        #pragma unroll
        for (int j = 0; j < 4; ++j) acc[i][j] = 0.f;

    for (int tap = 0; tap < TAPS; ++tap) {
        const int kd = tap / 9, kh = (tap / 3) % 3, kw = tap % 3;

        // load A tile (6144 floats = 1536 float4)
        {
            const float4* src = (const float4*)(g_wofft + tap*CIN*OC1P);
            float4* dst = (float4*)As;
            #pragma unroll
            for (int i = 0; i < 6; ++i) dst[tid + i*256] = src[tid + i*256];
        }
        // gather B tile: identity im2col (coords guaranteed in padded range)
        {
            const float* xb = g_xpt + ((((n*DP + dz + kd)*HP + hy + kh)*WP + wx + kw) << 6) + c0;
            #pragma unroll
            for (int j = 0; j < 4; ++j) {
                float4 v = *(const float4*)(xb + j*4);
                Bs[(c0 + j*4 + 0)*BNPOS + posl] = v.x;
                Bs[(c0 + j*4 + 1)*BNPOS + posl] = v.y;
                Bs[(c0 + j*4 + 2)*BNPOS + posl] = v.z;
                Bs[(c0 + j*4 + 3)*BNPOS + posl] = v.w;
            }
        }
        __syncthreads();

        #pragma unroll 8
        for (int c = 0; c < CIN; ++c) {
            float4 b4 = *(const float4*)&Bs[c*BNPOS + tn*4];
            float b[4] = {b4.x, b4.y, b4.z, b4.w};
            float a[6];
            #pragma unroll
            for (int i = 0; i < 6; ++i) a[i] = As[c*OC1P + tm*6 + i];
            #pragma unroll
            for (int i = 0; i < 6; ++i)
                #pragma unroll
                for (int j = 0; j < 4; ++j) acc[i][j] += a[i]*b[j];
        }
        __syncthreads();
    }

    const int pos_out = pos0 + tn*4;
    #pragma unroll
    for (int i = 0; i < 6; ++i) {
        int oc = tm*6 + i;
        if (oc < OC1) {
            float bias = b_off[oc];
            float4 v = make_float4(acc[i][0]+bias, acc[i][1]+bias, acc[i][2]+bias, acc[i][3]+bias);
            *(float4*)&g_off[oc*PTOT + pos_out] = v;
        }
    }
}

// ---------------- K2: deformable conv (GEMM 128 x 64pos, trilinear gather) --------
__global__ __launch_bounds__(256) void k_deform() {
    __shared__ float As[CIN*COUT];   // 32KB  [c][oc]
    __shared__ float Bs[CIN*BNPOS];  // 16KB  [c][pos]

    const int tid = threadIdx.x;
    const int pos0 = blockIdx.x * BNPOS;
    const int tn = tid & 15;          // 4 pos each
    const int tm = tid >> 4;          // 8 oc each

    const int posl = tid & 63;
    const int c0 = (tid >> 6) * 16;
    const int pos = pos0 + posl;
    const int n = pos / VOX;
    const int vox = pos % VOX;
    const int dz = vox / (HH*WW);
    const int r  = vox % (HH*WW);
    const int hy = r / WW;
    const int wx = r % WW;

    float acc[8][4];
    #pragma unroll
    for (int i = 0; i < 8; ++i)
        #pragma unroll
        for (int j = 0; j < 4; ++j) acc[i][j] = 0.f;

    for (int tap = 0; tap < TAPS; ++tap) {
        const int kd = tap / 9, kh = (tap / 3) % 3, kw = tap % 3;

        // load A tile (8192 floats = 2048 float4)
        {
            const float4* src = (const float4*)(g_wt + tap*CIN*COUT);
            float4* dst = (float4*)As;
            #pragma unroll
            for (int i = 0; i < 8; ++i) dst[tid + i*256] = src[tid + i*256];
        }
        // trilinear gather for this (tap, pos): 16 channels per thread
        {
            float od = g_off[(0*TAPS + tap)*PTOT + pos];
            float oh = g_off[(1*TAPS + tap)*PTOT + pos];
            float ow = g_off[(2*TAPS + tap)*PTOT + pos];
            float pd = od + (float)(dz + kd);
            float ph = oh + (float)(hy + kh);
            float pw = ow + (float)(wx + kw);
            float fpd = floorf(pd), fph = floorf(ph), fpw = floorf(pw);
            int d0 = (int)fpd, h0 = (int)fph, w0 = (int)fpw;
            float fd = pd - fpd, fh = ph - fph, fw = pw - fpw;

            float4 v0 = make_float4(0,0,0,0), v1 = v0, v2 = v0, v3 = v0;
            #pragma unroll
            for (int a = 0; a < 2; ++a) {
                int ddx = d0 + a;
                if (ddx < 0 || ddx >= DP) continue;
                float wa = a ? fd : 1.f - fd;
                #pragma unroll
                for (int b = 0; b < 2; ++b) {
                    int hhx = h0 + b;
                    if (hhx < 0 || hhx >= HP) continue;
                    float wb = wa * (b ? fh : 1.f - fh);
                    #pragma unroll
                    for (int cc = 0; cc < 2; ++cc) {
                        int wwx = w0 + cc;
                        if (wwx < 0 || wwx >= WP) continue;
                        float wgt = wb * (cc ? fw : 1.f - fw);
                        const float4* p = (const float4*)(g_xpt + ((((n*DP + ddx)*HP + hhx)*WP + wwx) << 6) + c0);
                        float4 x0 = p[0], x1 = p[1], x2 = p[2], x3 = p[3];
                        v0.x += wgt*x0.x; v0.y += wgt*x0.y; v0.z += wgt*x0.z; v0.w += wgt*x0.w;
                        v1.x += wgt*x1.x; v1.y += wgt*x1.y; v1.z += wgt*x1.z; v1.w += wgt*x1.w;
                        v2.x += wgt*x2.x; v2.y += wgt*x2.y; v2.z += wgt*x2.z; v2.w += wgt*x2.w;
                        v3.x += wgt*x3.x; v3.y += wgt*x3.y; v3.z += wgt*x3.z; v3.w += wgt*x3.w;
                    }
                }
            }
            Bs[(c0+ 0)*BNPOS + posl] = v0.x; Bs[(c0+ 1)*BNPOS + posl] = v0.y;
            Bs[(c0+ 2)*BNPOS + posl] = v0.z; Bs[(c0+ 3)*BNPOS + posl] = v0.w;
            Bs[(c0+ 4)*BNPOS + posl] = v1.x; Bs[(c0+ 5)*BNPOS + posl] = v1.y;
            Bs[(c0+ 6)*BNPOS + posl] = v1.z; Bs[(c0+ 7)*BNPOS + posl] = v1.w;
            Bs[(c0+ 8)*BNPOS + posl] = v2.x; Bs[(c0+ 9)*BNPOS + posl] = v2.y;
            Bs[(c0+10)*BNPOS + posl] = v2.z; Bs[(c0+11)*BNPOS + posl] = v2.w;
            Bs[(c0+12)*BNPOS + posl] = v3.x; Bs[(c0+13)*BNPOS + posl] = v3.y;
            Bs[(c0+14)*BNPOS + posl] = v3.z; Bs[(c0+15)*BNPOS + posl] = v3.w;
        }
        __syncthreads();

        #pragma unroll 8
        for (int c = 0; c < CIN; ++c) {
            float4 b4 = *(const float4*)&Bs[c*BNPOS + tn*4];
            float b[4] = {b4.x, b4.y, b4.z, b4.w};
            float a[8];
            float4 a0 = *(const float4*)&As[c*COUT + tm*8];
            float4 a1 = *(const float4*)&As[c*COUT + tm*8 + 4];
            a[0]=a0.x; a[1]=a0.y; a[2]=a0.z; a[3]=a0.w;
            a[4]=a1.x; a[5]=a1.y; a[6]=a1.z; a[7]=a1.w;
            #pragma unroll
            for (int i = 0; i < 8; ++i)
                #pragma unroll
                for (int j = 0; j < 4; ++j) acc[i][j] += a[i]*b[j];
        }
        __syncthreads();
    }

    const int pos_out = pos0 + tn*4;
    #pragma unroll
    for (int i = 0; i < 8; ++i) {
        int oc = tm*8 + i;
        float4 v = make_float4(acc[i][0], acc[i][1], acc[i][2], acc[i][3]);
        *(float4*)&g_y[oc*PTOT + pos_out] = v;
    }
}

// ---------------- K3: per-channel batch stats ----------------
__global__ void k_stats() {
    __shared__ float ss[256], ss2[256];
    const int ch = blockIdx.x;
    const int tid = threadIdx.x;
    const float* y = g_y + ch*PTOT;
    float s = 0.f, s2 = 0.f;
    for (int i = tid; i < PTOT; i += 256) {
        float v = y[i];
        s += v; s2 += v*v;
    }
    ss[tid] = s; ss2[tid] = s2;
    __syncthreads();
    for (int stp = 128; stp > 0; stp >>= 1) {
        if (tid < stp) { ss[tid] += ss[tid+stp]; ss2[tid] += ss2[tid+stp]; }
        __syncthreads();
    }
    if (tid == 0) {
        float mean = ss[0] / (float)PTOT;
        float var = ss2[0] / (float)PTOT - mean*mean;
        g_stats[ch] = mean;
        g_stats[COUT + ch] = rsqrtf(var + BN_EPS);
    }
}

// ---------------- K4: normalize + affine + ReLU ----------------
__global__ void k_norm(const float* __restrict__ gamma, const float* __restrict__ beta,
                       float* __restrict__ out) {
    int idx = blockIdx.x * blockDim.x + threadIdx.x;
    const int total = NB*COUT*VOX;
    if (idx >= total) return;
    int vox = idx % VOX;
    int t = idx / VOX;
    int co = t % COUT;
    int n = t / COUT;
    float v = g_y[co*PTOT + n*VOX + vox];
    float r = (v - g_stats[co]) * g_stats[COUT + co] * gamma[co] + beta[co];
    out[idx] = r > 0.f ? r : 0.f;
}

// ---------------- launch ----------------
extern "C" void kernel_launch(void* const* d_in, const int* in_sizes, int n_in,
                              void* d_out, int out_size) {
    const float* x      = (const float*)d_in[0];
    const float* w_off  = (const float*)d_in[1];
    const float* b_off  = (const float*)d_in[2];
    const float* w_conv = (const float*)d_in[3];
    const float* gamma  = (const float*)d_in[4];
    const float* beta   = (const float*)d_in[5];
    float* out = (float*)d_out;

    {
        int total = NB*DP*HP*WP*CIN;
        k_pad<<<(total + 255)/256, 256>>>(x);
    }
    {
        int total = TAPS*CIN*OC1P;
        k_wofft<<<(total + 255)/256, 256>>>(w_off);
    }
    {
        int total = TAPS*CIN*COUT;
        k_wtrans<<<(total + 255)/256, 256>>>(w_conv);
    }
    k_offconv<<<NBLK, 256>>>(b_off);
    k_deform<<<NBLK, 256>>>();
    k_stats<<<COUT, 256>>>();
    {
        int total = NB*COUT*VOX;
        k_norm<<<(total + 255)/256, 256>>>(gamma, beta, out);
    }
}